// round 7
// baseline (speedup 1.0000x reference)
#include <cuda_runtime.h>
#include <math.h>
#include <stdint.h>

#define NDET 512
#define NC   81
#define HW   784
#define NMS_THRESH 0.5
#define EPSV 1e-4
#define TAU  6e-6          // flag margin (iou units); worst-case f32 err ~1.2e-6
#define FLAG_CAP (1 << 16)
#define NTILE 36           // upper-triangular 8x8 tile count

// ---------------- scratch (static device memory) ----------------------------
__device__ __align__(16) float  g_Pf[2][NDET][HW];          // sorted probs (f32)
__device__ double        g_ud[2][NDET];                     // sorted row sums (f64)
__device__ __align__(16) float g_partial[2][2][NDET][NDET]; // [side][khalf] partials
__device__ __align__(16) unsigned int g_bits[2][NDET][16];  // packed mask rows
__device__ int           g_order[NDET];
__device__ int           g_nflag;
__device__ int           g_flags[FLAG_CAP];                 // (side<<20)|(i<<10)|j

// ---------------- 1. sigmoid-gather + inline rank + row sums ----------------
__global__ void prob_kernel(const float* __restrict__ left,
                            const float* __restrict__ right,
                            const float* __restrict__ scores,
                            const int*   __restrict__ labels,
                            float*       __restrict__ out) {
    int b = blockIdx.x;
    int side = b >> 9;
    int n = b & (NDET - 1);
    int tid = threadIdx.x;

    if (b == 0 && tid == 0) g_nflag = 0;

    // rank of n under stable argsort(-scores)
    __shared__ int s_cnt;
    if (tid == 0) s_cnt = 0;
    __syncthreads();
    float sn = __ldg(&scores[n]);
    int c = 0;
    for (int j = tid; j < NDET; j += 256) {
        float sj = __ldg(&scores[j]);
        c += (sj > sn) || (sj == sn && j < n);
    }
    for (int o = 16; o; o >>= 1) c += __shfl_down_sync(0xffffffffu, c, o);
    if ((tid & 31) == 0) atomicAdd(&s_cnt, c);
    __syncthreads();
    int r = s_cnt;
    if (side == 0 && tid == 0) g_order[r] = n;

    const float* base = side ? right : left;
    int cls = labels[n];
    const float* row = base + ((size_t)n * NC + cls) * HW;
    float* orow = out + ((size_t)side * NDET + n) * HW;
    float* prow = g_Pf[side][r];

    double s = 0.0;
    for (int k = tid; k < HW; k += 256) {
        float x = row[k];
        float p = 1.0f / (1.0f + expf(-x));
        orow[k] = p;
        prow[k] = p;
        s += (double)p;
    }
    __shared__ double red[8];
    for (int o = 16; o; o >>= 1) s += __shfl_down_sync(0xffffffffu, s, o);
    if ((tid & 31) == 0) red[tid >> 5] = s;
    __syncthreads();
    if (tid == 0) {
        double tt = 0.0;
#pragma unroll
        for (int w = 0; w < 8; ++w) tt += red[w];
        g_ud[side][r] = tt;
    }
}

// ---------------- 2. f32 Gram partials: compact tri grid + reg prefetch -----
// grid 144 linear: blockIdx.x = z*NTILE + t, z = side*2 + khalf. All blocks live.
__global__ void __launch_bounds__(256) gemm_partial_kernel() {
    int t = blockIdx.x % NTILE;
    int z = blockIdx.x / NTILE;
    int khalf = z & 1, side = z >> 1;
    int by = 0, rem = t;
    while (rem >= 8 - by) { rem -= 8 - by; ++by; }
    int bx = by + rem;                 // bx >= by (upper triangle)
    int arow0 = by * 64, brow0 = bx * 64;
    int kbeg = khalf ? 400 : 0;
    int kend = khalf ? HW : 400;

    __shared__ __align__(16) float As[16][68];
    __shared__ __align__(16) float Bs[16][68];
    int tid = threadIdx.x;
    int tx = tid & 15, ty = tid >> 4;
    const float* P = &g_Pf[side][0][0];

    float s[4][4];
#pragma unroll
    for (int m = 0; m < 4; ++m)
#pragma unroll
        for (int n = 0; n < 4; ++n) s[m][n] = 0.0f;

    int rr = tid >> 2, kq = (tid & 3) * 4;
    const float* aptr = &P[(size_t)(arow0 + rr) * HW + kq];
    const float* bptr = &P[(size_t)(brow0 + rr) * HW + kq];

    float4 av = *(const float4*)&aptr[kbeg];
    float4 bv = *(const float4*)&bptr[kbeg];
    for (int kt = kbeg; kt < kend; kt += 16) {
        As[kq + 0][rr] = av.x; As[kq + 1][rr] = av.y;
        As[kq + 2][rr] = av.z; As[kq + 3][rr] = av.w;
        Bs[kq + 0][rr] = bv.x; Bs[kq + 1][rr] = bv.y;
        Bs[kq + 2][rr] = bv.z; Bs[kq + 3][rr] = bv.w;
        __syncthreads();
        if (kt + 16 < kend) {           // prefetch next k-tile during compute
            av = *(const float4*)&aptr[kt + 16];
            bv = *(const float4*)&bptr[kt + 16];
        }
        float tacc[4][4];
#pragma unroll
        for (int m = 0; m < 4; ++m)
#pragma unroll
            for (int n = 0; n < 4; ++n) tacc[m][n] = 0.0f;
#pragma unroll
        for (int kk = 0; kk < 16; ++kk) {
            float4 a4 = *(const float4*)&As[kk][ty * 4];
            float4 b4 = *(const float4*)&Bs[kk][tx * 4];
            float a[4] = {a4.x, a4.y, a4.z, a4.w};
            float bb[4] = {b4.x, b4.y, b4.z, b4.w};
#pragma unroll
            for (int m = 0; m < 4; ++m)
#pragma unroll
                for (int n = 0; n < 4; ++n) tacc[m][n] = fmaf(a[m], bb[n], tacc[m][n]);
        }
#pragma unroll
        for (int m = 0; m < 4; ++m)
#pragma unroll
            for (int n = 0; n < 4; ++n) s[m][n] = __fadd_rn(s[m][n], tacc[m][n]);
        __syncthreads();
    }

    float* dst = &g_partial[side][khalf][0][0];
#pragma unroll
    for (int m = 0; m < 4; ++m) {
        int gi = arow0 + ty * 4 + m;
        float4 v = make_float4(s[m][0], s[m][1], s[m][2], s[m][3]);
        *(float4*)&dst[(size_t)gi * NDET + brow0 + tx * 4] = v;
    }
}

// ---------------- 3. combine halves (f64), threshold, pack bits, flags ------
// grid (256, 2), 256 threads: 2 rows per block, 128 thr/row, 4 j's per thread.
__global__ void epilogue_kernel() {
    int side = blockIdx.y;
    int tid = threadIdx.x;
    int rloc = tid >> 7;                 // 0..1
    int i = blockIdx.x * 2 + rloc;
    int tt = tid & 127;
    __shared__ unsigned int words[2][16];
    if (tid < 32) words[tid >> 4][tid & 15] = 0;
    __syncthreads();

    double den = g_ud[side][i] + EPSV;
    int j0 = tt * 4;
    float4 a = *(const float4*)&g_partial[side][0][i][j0];
    float4 b = *(const float4*)&g_partial[side][1][i][j0];
    float pa[4] = {a.x, a.y, a.z, a.w};
    float pb[4] = {b.x, b.y, b.z, b.w};
    unsigned int nib = 0;
#pragma unroll
    for (int n = 0; n < 4; ++n) {
        double inter = (double)pa[n] + (double)pb[n];
        double mg = inter - 0.5 * den;
        if (mg >= 0.0) nib |= (1u << n);
        int gj = j0 + n;
        if (gj > i && fabs(mg) <= TAU * den) {
            int idx = atomicAdd(&g_nflag, 1);
            if (idx < FLAG_CAP)
                g_flags[idx] = (side << 20) | (i << 10) | gj;
        }
    }
    atomicOr(&words[rloc][tt >> 3], nib << ((tt & 7) * 4));
    __syncthreads();
    if (tid < 32) g_bits[side][blockIdx.x * 2 + (tid >> 4)][tid & 15] = words[tid >> 4][tid & 15];
}

// ---------------- 4. post: exact f64 refine + skip-NMS + finalize -----------
// single block, 512 threads
__global__ void post_kernel(float* __restrict__ out, int out_size) {
    int tid = threadIdx.x;
    int lane = tid & 31;
    int warp = tid >> 5;
    __shared__ unsigned int s_sup[2][16];

    // 4a. refine near-threshold pairs in exact f64 (16 warps)
    int nf = g_nflag;
    if (nf > FLAG_CAP) nf = FLAG_CAP;
    for (int p = warp; p < nf; p += 16) {
        int v = g_flags[p];
        int side = v >> 20, i = (v >> 10) & 1023, j = v & 1023;
        const float* Pi = g_Pf[side][i];
        const float* Pj = g_Pf[side][j];
        double sum = 0.0;
#pragma unroll
        for (int q = 0; q < 25; ++q) {
            int k = lane + q * 32;
            float a = (k < HW) ? Pi[k] : 0.0f;
            float b = (k < HW) ? Pj[k] : 0.0f;
            sum = fma((double)a, (double)b, sum);
        }
        for (int o = 16; o; o >>= 1) sum += __shfl_down_sync(0xffffffffu, sum, o);
        if (lane == 0) {
            double den = g_ud[side][i] + EPSV;
            unsigned int bit = 1u << (j & 31);
            unsigned int* w = &g_bits[side][i][j >> 5];
            if (sum / den >= NMS_THRESH) atomicOr(w, bit);
            else                         atomicAnd(w, ~bit);
        }
    }
    __syncthreads();

    // 4b. greedy skip-NMS: warp 0 -> side 0, warp 1 -> side 1 (parallel)
    if (warp < 2) {
        int side = warp;
        unsigned int removed = 0;   // lane w<16 holds suppression word w
        int i = 0;                  // top-ranked row always kept
        while (true) {
            int rw = i >> 5, rbit = i & 31;
            unsigned int hi = (rbit == 31) ? 0u : (0xFFFFFFFFu << (rbit + 1));
            unsigned int m = (lane < 16) ? g_bits[side][i][lane] : 0u;
            if (lane < rw) m = 0u;
            else if (lane == rw) m &= hi;
            removed |= m;
            unsigned int cand = (lane < 16) ? ~removed : 0u;
            if (lane < rw) cand = 0u;
            else if (lane == rw) cand &= hi;
            unsigned int ball = __ballot_sync(0xffffffffu, cand != 0u);
            if (!ball) break;
            int w = __ffs(ball) - 1;
            unsigned int word = __shfl_sync(0xffffffffu, cand, w);
            i = w * 32 + __ffs(word) - 1;
        }
        if (lane < 16) s_sup[side][lane] = removed;
    }
    __syncthreads();

    // 4c. finalize: keep[order[r]] = valid & !supL & !supR
    int r = tid;
    int n = g_order[r];
    bool valid = (g_ud[0][r] > 0.0) && (g_ud[1][r] > 0.0);
    bool supL = (s_sup[0][r >> 5] >> (r & 31)) & 1u;
    bool supR = (s_sup[1][r >> 5] >> (r & 31)) & 1u;
    float k = (valid && !supL && !supR) ? 1.0f : 0.0f;
    if (out_size >= 2 * NDET * HW + NDET)
        out[2 * NDET * HW + n] = k;
}

// ---------------- launch -----------------------------------------------------
extern "C" void kernel_launch(void* const* d_in, const int* in_sizes, int n_in,
                              void* d_out, int out_size) {
    const float* left   = (const float*)d_in[0];
    const float* right  = (const float*)d_in[1];
    const float* scores = (const float*)d_in[2];
    const int*   labels = (const int*)d_in[3];
    float* out = (float*)d_out;
    (void)in_sizes; (void)n_in;

    prob_kernel<<<2 * NDET, 256>>>(left, right, scores, labels, out);
    gemm_partial_kernel<<<4 * NTILE, 256>>>();
    dim3 egrid(NDET / 2, 2);
    epilogue_kernel<<<egrid, 256>>>();
    post_kernel<<<1, NDET>>>(out, out_size);
}

// round 8
// speedup vs baseline: 2.4243x; 2.4243x over previous
#include <cuda_runtime.h>
#include <math.h>
#include <stdint.h>

#define NDET 512
#define NC   81
#define HW   784
#define NMS_THRESH 0.5
#define EPSV 1e-4
#define TAU  6e-6          // flag margin (iou units); worst-case f32 err ~1.2e-6
#define FLAG_CAP (1 << 16)
#define NTILE 36           // upper-triangular 8x8 tile count

// ---------------- scratch (static device memory) ----------------------------
__device__ __align__(16) float  g_Pf[2][NDET][HW];          // sorted probs (f32)
__device__ double        g_ud[2][NDET];                     // sorted row sums (f64)
__device__ __align__(16) float g_partial[2][2][NDET][NDET]; // [side][khalf] partials
__device__ __align__(16) unsigned int g_bits[2][NDET][16];  // packed mask rows
__device__ int           g_order[NDET];
__device__ int           g_nflag;
__device__ int           g_flags[FLAG_CAP];                 // (side<<20)|(i<<10)|j

// ---------------- 1. sigmoid-gather + inline rank + row sums ----------------
__global__ void prob_kernel(const float* __restrict__ left,
                            const float* __restrict__ right,
                            const float* __restrict__ scores,
                            const int*   __restrict__ labels,
                            float*       __restrict__ out) {
    int b = blockIdx.x;
    int side = b >> 9;
    int n = b & (NDET - 1);
    int tid = threadIdx.x;

    if (b == 0 && tid == 0) g_nflag = 0;

    // rank of n under stable argsort(-scores)
    __shared__ int s_cnt;
    if (tid == 0) s_cnt = 0;
    __syncthreads();
    float sn = __ldg(&scores[n]);
    int c = 0;
    for (int j = tid; j < NDET; j += 256) {
        float sj = __ldg(&scores[j]);
        c += (sj > sn) || (sj == sn && j < n);
    }
    for (int o = 16; o; o >>= 1) c += __shfl_down_sync(0xffffffffu, c, o);
    if ((tid & 31) == 0) atomicAdd(&s_cnt, c);
    __syncthreads();
    int r = s_cnt;
    if (side == 0 && tid == 0) g_order[r] = n;

    const float* base = side ? right : left;
    int cls = labels[n];
    const float* row = base + ((size_t)n * NC + cls) * HW;
    float* orow = out + ((size_t)side * NDET + n) * HW;
    float* prow = g_Pf[side][r];

    double s = 0.0;
    for (int k = tid; k < HW; k += 256) {
        float x = row[k];
        float p = 1.0f / (1.0f + expf(-x));
        orow[k] = p;
        prow[k] = p;
        s += (double)p;
    }
    __shared__ double red[8];
    for (int o = 16; o; o >>= 1) s += __shfl_down_sync(0xffffffffu, s, o);
    if ((tid & 31) == 0) red[tid >> 5] = s;
    __syncthreads();
    if (tid == 0) {
        double tt = 0.0;
#pragma unroll
        for (int w = 0; w < 8; ++w) tt += red[w];
        g_ud[side][r] = tt;
    }
}

// ---------------- 2. f32 Gram partials: compact tri grid + reg prefetch -----
// grid 144 linear: blockIdx.x = z*NTILE + t, z = side*2 + khalf. All blocks live.
__global__ void __launch_bounds__(256) gemm_partial_kernel() {
    int t = blockIdx.x % NTILE;
    int z = blockIdx.x / NTILE;
    int khalf = z & 1, side = z >> 1;
    int by = 0, rem = t;
    while (rem >= 8 - by) { rem -= 8 - by; ++by; }
    int bx = by + rem;                 // bx >= by (upper triangle)
    int arow0 = by * 64, brow0 = bx * 64;
    int kbeg = khalf ? 400 : 0;
    int kend = khalf ? HW : 400;

    __shared__ __align__(16) float As[16][68];
    __shared__ __align__(16) float Bs[16][68];
    int tid = threadIdx.x;
    int tx = tid & 15, ty = tid >> 4;
    const float* P = &g_Pf[side][0][0];

    float s[4][4];
#pragma unroll
    for (int m = 0; m < 4; ++m)
#pragma unroll
        for (int n = 0; n < 4; ++n) s[m][n] = 0.0f;

    int rr = tid >> 2, kq = (tid & 3) * 4;
    const float* aptr = &P[(size_t)(arow0 + rr) * HW + kq];
    const float* bptr = &P[(size_t)(brow0 + rr) * HW + kq];

    float4 av = *(const float4*)&aptr[kbeg];
    float4 bv = *(const float4*)&bptr[kbeg];
    for (int kt = kbeg; kt < kend; kt += 16) {
        As[kq + 0][rr] = av.x; As[kq + 1][rr] = av.y;
        As[kq + 2][rr] = av.z; As[kq + 3][rr] = av.w;
        Bs[kq + 0][rr] = bv.x; Bs[kq + 1][rr] = bv.y;
        Bs[kq + 2][rr] = bv.z; Bs[kq + 3][rr] = bv.w;
        __syncthreads();
        if (kt + 16 < kend) {           // prefetch next k-tile during compute
            av = *(const float4*)&aptr[kt + 16];
            bv = *(const float4*)&bptr[kt + 16];
        }
        float tacc[4][4];
#pragma unroll
        for (int m = 0; m < 4; ++m)
#pragma unroll
            for (int n = 0; n < 4; ++n) tacc[m][n] = 0.0f;
#pragma unroll
        for (int kk = 0; kk < 16; ++kk) {
            float4 a4 = *(const float4*)&As[kk][ty * 4];
            float4 b4 = *(const float4*)&Bs[kk][tx * 4];
            float a[4] = {a4.x, a4.y, a4.z, a4.w};
            float bb[4] = {b4.x, b4.y, b4.z, b4.w};
#pragma unroll
            for (int m = 0; m < 4; ++m)
#pragma unroll
                for (int n = 0; n < 4; ++n) tacc[m][n] = fmaf(a[m], bb[n], tacc[m][n]);
        }
#pragma unroll
        for (int m = 0; m < 4; ++m)
#pragma unroll
            for (int n = 0; n < 4; ++n) s[m][n] = __fadd_rn(s[m][n], tacc[m][n]);
        __syncthreads();
    }

    float* dst = &g_partial[side][khalf][0][0];
#pragma unroll
    for (int m = 0; m < 4; ++m) {
        int gi = arow0 + ty * 4 + m;
        float4 v = make_float4(s[m][0], s[m][1], s[m][2], s[m][3]);
        *(float4*)&dst[(size_t)gi * NDET + brow0 + tx * 4] = v;
    }
}

// ---------------- 3. combine halves (f64), threshold, pack bits, flags ------
// grid (256, 2), 256 threads: 2 rows per block, 128 thr/row, 4 j's per thread.
__global__ void epilogue_kernel() {
    int side = blockIdx.y;
    int tid = threadIdx.x;
    int rloc = tid >> 7;                 // 0..1
    int i = blockIdx.x * 2 + rloc;
    int tt = tid & 127;
    __shared__ unsigned int words[2][16];
    if (tid < 32) words[tid >> 4][tid & 15] = 0;
    __syncthreads();

    double den = g_ud[side][i] + EPSV;
    int j0 = tt * 4;
    float4 a = *(const float4*)&g_partial[side][0][i][j0];
    float4 b = *(const float4*)&g_partial[side][1][i][j0];
    float pa[4] = {a.x, a.y, a.z, a.w};
    float pb[4] = {b.x, b.y, b.z, b.w};
    unsigned int nib = 0;
#pragma unroll
    for (int n = 0; n < 4; ++n) {
        double inter = (double)pa[n] + (double)pb[n];
        double mg = inter - 0.5 * den;
        if (mg >= 0.0) nib |= (1u << n);
        int gj = j0 + n;
        if (gj > i && fabs(mg) <= TAU * den) {
            int idx = atomicAdd(&g_nflag, 1);
            if (idx < FLAG_CAP)
                g_flags[idx] = (side << 20) | (i << 10) | gj;
        }
    }
    atomicOr(&words[rloc][tt >> 3], nib << ((tt & 7) * 4));
    __syncthreads();
    if (tid < 32) g_bits[side][blockIdx.x * 2 + (tid >> 4)][tid & 15] = words[tid >> 4][tid & 15];
}

// ---------------- 4. exact f64 refine: warp/pair, float4 loads, wide grid ---
__global__ void refine_kernel() {
    int lane = threadIdx.x & 31;
    int warp = (blockIdx.x * blockDim.x + threadIdx.x) >> 5;
    int nwarps = (gridDim.x * blockDim.x) >> 5;
    int n = g_nflag;
    if (n > FLAG_CAP) n = FLAG_CAP;
    for (int p = warp; p < n; p += nwarps) {
        int v = g_flags[p];
        int side = v >> 20, i = (v >> 10) & 1023, j = v & 1023;
        const float4* Pi = (const float4*)g_Pf[side][i];
        const float4* Pj = (const float4*)g_Pf[side][j];
        double sum = 0.0;
#pragma unroll
        for (int q = 0; q < 7; ++q) {           // 196 float4s per row (784/4)
            int k = lane + q * 32;
            float4 a = (k < 196) ? Pi[k] : make_float4(0.f, 0.f, 0.f, 0.f);
            float4 b = (k < 196) ? Pj[k] : make_float4(0.f, 0.f, 0.f, 0.f);
            sum = fma((double)a.x, (double)b.x, sum);
            sum = fma((double)a.y, (double)b.y, sum);
            sum = fma((double)a.z, (double)b.z, sum);
            sum = fma((double)a.w, (double)b.w, sum);
        }
        for (int o = 16; o; o >>= 1) sum += __shfl_down_sync(0xffffffffu, sum, o);
        if (lane == 0) {
            double den = g_ud[side][i] + EPSV;
            unsigned int bit = 1u << (j & 31);
            unsigned int* w = &g_bits[side][i][j >> 5];
            if (sum / den >= NMS_THRESH) atomicOr(w, bit);
            else                         atomicAnd(w, ~bit);
        }
    }
}

// ---------------- 5. skip-NMS (warps 0/1) + finalize, one block -------------
__global__ void nmsfin_kernel(float* __restrict__ out, int out_size) {
    int tid = threadIdx.x;
    int lane = tid & 31;
    int warp = tid >> 5;
    __shared__ unsigned int s_sup[2][16];

    if (warp < 2) {
        int side = warp;
        unsigned int removed = 0;   // lane w<16 holds suppression word w
        int i = 0;                  // top-ranked row always kept
        while (true) {
            int rw = i >> 5, rbit = i & 31;
            unsigned int hi = (rbit == 31) ? 0u : (0xFFFFFFFFu << (rbit + 1));
            unsigned int m = (lane < 16) ? g_bits[side][i][lane] : 0u;
            if (lane < rw) m = 0u;
            else if (lane == rw) m &= hi;
            removed |= m;
            unsigned int cand = (lane < 16) ? ~removed : 0u;
            if (lane < rw) cand = 0u;
            else if (lane == rw) cand &= hi;
            unsigned int ball = __ballot_sync(0xffffffffu, cand != 0u);
            if (!ball) break;
            int w = __ffs(ball) - 1;
            unsigned int word = __shfl_sync(0xffffffffu, cand, w);
            i = w * 32 + __ffs(word) - 1;
        }
        if (lane < 16) s_sup[side][lane] = removed;
    }
    __syncthreads();

    int r = tid;
    int n = g_order[r];
    bool valid = (g_ud[0][r] > 0.0) && (g_ud[1][r] > 0.0);
    bool supL = (s_sup[0][r >> 5] >> (r & 31)) & 1u;
    bool supR = (s_sup[1][r >> 5] >> (r & 31)) & 1u;
    float k = (valid && !supL && !supR) ? 1.0f : 0.0f;
    if (out_size >= 2 * NDET * HW + NDET)
        out[2 * NDET * HW + n] = k;
}

// ---------------- launch -----------------------------------------------------
extern "C" void kernel_launch(void* const* d_in, const int* in_sizes, int n_in,
                              void* d_out, int out_size) {
    const float* left   = (const float*)d_in[0];
    const float* right  = (const float*)d_in[1];
    const float* scores = (const float*)d_in[2];
    const int*   labels = (const int*)d_in[3];
    float* out = (float*)d_out;
    (void)in_sizes; (void)n_in;

    prob_kernel<<<2 * NDET, 256>>>(left, right, scores, labels, out);
    gemm_partial_kernel<<<4 * NTILE, 256>>>();
    dim3 egrid(NDET / 2, 2);
    epilogue_kernel<<<egrid, 256>>>();
    refine_kernel<<<132, 256>>>();
    nmsfin_kernel<<<1, NDET>>>(out, out_size);
}

// round 9
// speedup vs baseline: 2.5562x; 1.0544x over previous
#include <cuda_runtime.h>
#include <math.h>
#include <stdint.h>

#define NDET 512
#define NC   81
#define HW   784
#define NMS_THRESH 0.5
#define EPSV 1e-4
#define TAU  6e-6          // flag margin (iou units); worst-case f32 err ~1.2e-6
#define NTILE 36           // upper-triangular 8x8 tile count

// ---------------- scratch (static device memory) ----------------------------
__device__ __align__(16) float  g_Pf[2][NDET][HW];          // sorted probs (f32)
__device__ double        g_ud[2][NDET];                     // sorted row sums (f64)
__device__ __align__(16) float g_partial[2][2][NDET][NDET]; // [side][khalf] partials
__device__ __align__(16) unsigned int g_bits[2][NDET][16];  // packed mask rows
__device__ int           g_order[NDET];

// ---------------- 1. sigmoid-gather + inline rank + row sums (both sides) ---
// grid 512 x 256 thr: block n handles left AND right rows (rank computed once).
__global__ void prob_kernel(const float* __restrict__ left,
                            const float* __restrict__ right,
                            const float* __restrict__ scores,
                            const int*   __restrict__ labels,
                            float*       __restrict__ out) {
    int n = blockIdx.x;
    int tid = threadIdx.x;

    // rank of n under stable argsort(-scores)
    __shared__ int s_cnt;
    if (tid == 0) s_cnt = 0;
    __syncthreads();
    float sn = __ldg(&scores[n]);
    int c = 0;
    for (int j = tid; j < NDET; j += 256) {
        float sj = __ldg(&scores[j]);
        c += (sj > sn) || (sj == sn && j < n);
    }
    for (int o = 16; o; o >>= 1) c += __shfl_down_sync(0xffffffffu, c, o);
    if ((tid & 31) == 0) atomicAdd(&s_cnt, c);
    __syncthreads();
    int r = s_cnt;
    if (tid == 0) g_order[r] = n;

    int cls = labels[n];
    __shared__ double red[8];
#pragma unroll
    for (int side = 0; side < 2; ++side) {
        const float* base = side ? right : left;
        const float* row = base + ((size_t)n * NC + cls) * HW;
        float* orow = out + ((size_t)side * NDET + n) * HW;
        float* prow = g_Pf[side][r];

        double s = 0.0;
        for (int k = tid; k < HW; k += 256) {
            float x = row[k];
            float p = 1.0f / (1.0f + expf(-x));
            orow[k] = p;
            prow[k] = p;
            s += (double)p;
        }
        for (int o = 16; o; o >>= 1) s += __shfl_down_sync(0xffffffffu, s, o);
        if ((tid & 31) == 0) red[tid >> 5] = s;
        __syncthreads();
        if (tid == 0) {
            double tt = 0.0;
#pragma unroll
            for (int w = 0; w < 8; ++w) tt += red[w];
            g_ud[side][r] = tt;
        }
        __syncthreads();
    }
}

// ---------------- 2. f32 Gram partials: compact tri grid + reg prefetch -----
// grid 144 linear: blockIdx.x = z*NTILE + t, z = side*2 + khalf. All blocks live.
__global__ void __launch_bounds__(256) gemm_partial_kernel() {
    int t = blockIdx.x % NTILE;
    int z = blockIdx.x / NTILE;
    int khalf = z & 1, side = z >> 1;
    int by = 0, rem = t;
    while (rem >= 8 - by) { rem -= 8 - by; ++by; }
    int bx = by + rem;                 // bx >= by (upper triangle)
    int arow0 = by * 64, brow0 = bx * 64;
    int kbeg = khalf ? 400 : 0;
    int kend = khalf ? HW : 400;

    __shared__ __align__(16) float As[16][68];
    __shared__ __align__(16) float Bs[16][68];
    int tid = threadIdx.x;
    int tx = tid & 15, ty = tid >> 4;
    const float* P = &g_Pf[side][0][0];

    float s[4][4];
#pragma unroll
    for (int m = 0; m < 4; ++m)
#pragma unroll
        for (int n = 0; n < 4; ++n) s[m][n] = 0.0f;

    int rr = tid >> 2, kq = (tid & 3) * 4;
    const float* aptr = &P[(size_t)(arow0 + rr) * HW + kq];
    const float* bptr = &P[(size_t)(brow0 + rr) * HW + kq];

    float4 av = *(const float4*)&aptr[kbeg];
    float4 bv = *(const float4*)&bptr[kbeg];
    for (int kt = kbeg; kt < kend; kt += 16) {
        As[kq + 0][rr] = av.x; As[kq + 1][rr] = av.y;
        As[kq + 2][rr] = av.z; As[kq + 3][rr] = av.w;
        Bs[kq + 0][rr] = bv.x; Bs[kq + 1][rr] = bv.y;
        Bs[kq + 2][rr] = bv.z; Bs[kq + 3][rr] = bv.w;
        __syncthreads();
        if (kt + 16 < kend) {           // prefetch next k-tile during compute
            av = *(const float4*)&aptr[kt + 16];
            bv = *(const float4*)&bptr[kt + 16];
        }
        float tacc[4][4];
#pragma unroll
        for (int m = 0; m < 4; ++m)
#pragma unroll
            for (int n = 0; n < 4; ++n) tacc[m][n] = 0.0f;
#pragma unroll
        for (int kk = 0; kk < 16; ++kk) {
            float4 a4 = *(const float4*)&As[kk][ty * 4];
            float4 b4 = *(const float4*)&Bs[kk][tx * 4];
            float a[4] = {a4.x, a4.y, a4.z, a4.w};
            float bb[4] = {b4.x, b4.y, b4.z, b4.w};
#pragma unroll
            for (int m = 0; m < 4; ++m)
#pragma unroll
                for (int n = 0; n < 4; ++n) tacc[m][n] = fmaf(a[m], bb[n], tacc[m][n]);
        }
#pragma unroll
        for (int m = 0; m < 4; ++m)
#pragma unroll
            for (int n = 0; n < 4; ++n) s[m][n] = __fadd_rn(s[m][n], tacc[m][n]);
        __syncthreads();
    }

    float* dst = &g_partial[side][khalf][0][0];
#pragma unroll
    for (int m = 0; m < 4; ++m) {
        int gi = arow0 + ty * 4 + m;
        float4 v = make_float4(s[m][0], s[m][1], s[m][2], s[m][3]);
        *(float4*)&dst[(size_t)gi * NDET + brow0 + tx * 4] = v;
    }
}

// ---------------- 3. epilogue: combine, threshold, INLINE f64 refine, pack --
// grid (256, 2), 256 threads: 2 rows/block; warps 0-3 row0, warps 4-7 row1.
// Near-threshold pairs refined warp-cooperatively (exact f64 dot) in place.
__global__ void epilogue_kernel() {
    int side = blockIdx.y;
    int tid = threadIdx.x;
    int lane = tid & 31;
    int rloc = tid >> 7;                 // 0..1 (warp-uniform)
    int i = blockIdx.x * 2 + rloc;
    int tt = tid & 127;
    __shared__ unsigned int words[2][16];
    if (tid < 32) words[tid >> 4][tid & 15] = 0;
    __syncthreads();

    double den = g_ud[side][i] + EPSV;
    int j0 = tt * 4;
    float4 a = *(const float4*)&g_partial[side][0][i][j0];
    float4 b = *(const float4*)&g_partial[side][1][i][j0];
    float pa[4] = {a.x, a.y, a.z, a.w};
    float pb[4] = {b.x, b.y, b.z, b.w};
    unsigned int nib = 0, pend = 0;
#pragma unroll
    for (int n = 0; n < 4; ++n) {
        double inter = (double)pa[n] + (double)pb[n];
        double mg = inter - 0.5 * den;
        if (mg >= 0.0) nib |= (1u << n);
        if (j0 + n > i && fabs(mg) <= TAU * den) pend |= (1u << n);
    }

    // warp-cooperative exact refinement of flagged pairs (i is warp-uniform)
    const float4* Pi = (const float4*)g_Pf[side][i];
    while (true) {
        unsigned int bal = __ballot_sync(0xffffffffu, pend != 0u);
        if (!bal) break;
        int src = __ffs(bal) - 1;
        unsigned int pw = __shfl_sync(0xffffffffu, pend, src);
        int n = __ffs(pw) - 1;
        int gj = __shfl_sync(0xffffffffu, j0, src) + n;
        const float4* Pj = (const float4*)g_Pf[side][gj];
        double s0 = 0.0, s1 = 0.0, s2 = 0.0, s3 = 0.0;
#pragma unroll
        for (int q = 0; q < 7; ++q) {           // 196 float4 per row
            int k = lane + q * 32;
            float4 x = (k < 196) ? Pi[k] : make_float4(0.f, 0.f, 0.f, 0.f);
            float4 y = (k < 196) ? Pj[k] : make_float4(0.f, 0.f, 0.f, 0.f);
            s0 = fma((double)x.x, (double)y.x, s0);
            s1 = fma((double)x.y, (double)y.y, s1);
            s2 = fma((double)x.z, (double)y.z, s2);
            s3 = fma((double)x.w, (double)y.w, s3);
        }
        double sum = (s0 + s1) + (s2 + s3);
        for (int o = 16; o; o >>= 1) sum += __shfl_down_sync(0xffffffffu, sum, o);
        sum = __shfl_sync(0xffffffffu, sum, 0);
        if (lane == src) {
            if (sum / den >= NMS_THRESH) nib |= (1u << n);
            else                         nib &= ~(1u << n);
            pend &= ~(1u << n);
        }
    }

    atomicOr(&words[rloc][tt >> 3], nib << ((tt & 7) * 4));
    __syncthreads();
    if (tid < 32)
        g_bits[side][blockIdx.x * 2 + (tid >> 4)][tid & 15] = words[tid >> 4][tid & 15];
}

// ---------------- 4. skip-NMS (warps 0/1) + finalize, one block -------------
__global__ void nmsfin_kernel(float* __restrict__ out, int out_size) {
    int tid = threadIdx.x;
    int lane = tid & 31;
    int warp = tid >> 5;
    __shared__ unsigned int s_sup[2][16];

    if (warp < 2) {
        int side = warp;
        unsigned int removed = 0;   // lane w<16 holds suppression word w
        int i = 0;                  // top-ranked row always kept
        while (true) {
            int rw = i >> 5, rbit = i & 31;
            unsigned int hi = (rbit == 31) ? 0u : (0xFFFFFFFFu << (rbit + 1));
            unsigned int m = (lane < 16) ? g_bits[side][i][lane] : 0u;
            if (lane < rw) m = 0u;
            else if (lane == rw) m &= hi;
            removed |= m;
            unsigned int cand = (lane < 16) ? ~removed : 0u;
            if (lane < rw) cand = 0u;
            else if (lane == rw) cand &= hi;
            unsigned int ball = __ballot_sync(0xffffffffu, cand != 0u);
            if (!ball) break;
            int w = __ffs(ball) - 1;
            unsigned int word = __shfl_sync(0xffffffffu, cand, w);
            i = w * 32 + __ffs(word) - 1;
        }
        if (lane < 16) s_sup[side][lane] = removed;
    }
    __syncthreads();

    int r = tid;
    int n = g_order[r];
    bool valid = (g_ud[0][r] > 0.0) && (g_ud[1][r] > 0.0);
    bool supL = (s_sup[0][r >> 5] >> (r & 31)) & 1u;
    bool supR = (s_sup[1][r >> 5] >> (r & 31)) & 1u;
    float k = (valid && !supL && !supR) ? 1.0f : 0.0f;
    if (out_size >= 2 * NDET * HW + NDET)
        out[2 * NDET * HW + n] = k;
}

// ---------------- launch -----------------------------------------------------
extern "C" void kernel_launch(void* const* d_in, const int* in_sizes, int n_in,
                              void* d_out, int out_size) {
    const float* left   = (const float*)d_in[0];
    const float* right  = (const float*)d_in[1];
    const float* scores = (const float*)d_in[2];
    const int*   labels = (const int*)d_in[3];
    float* out = (float*)d_out;
    (void)in_sizes; (void)n_in;

    prob_kernel<<<NDET, 256>>>(left, right, scores, labels, out);
    gemm_partial_kernel<<<4 * NTILE, 256>>>();
    dim3 egrid(NDET / 2, 2);
    epilogue_kernel<<<egrid, 256>>>();
    nmsfin_kernel<<<1, NDET>>>(out, out_size);
}

// round 10
// speedup vs baseline: 2.7160x; 1.0625x over previous
#include <cuda_runtime.h>
#include <math.h>
#include <stdint.h>

#define NDET 512
#define NC   81
#define HW   784
#define HW4  196           // HW / 4
#define NMS_THRESH 0.5
#define EPSV 1e-4
#define TAU  6e-6          // flag margin (iou units); worst-case f32 err ~1.2e-6
#define NTILE 36           // upper-triangular 8x8 tile count

// ---------------- scratch (static device memory) ----------------------------
__device__ __align__(16) float  g_Pf[2][NDET][HW];          // sorted probs (f32)
__device__ double        g_ud[2][NDET];                     // sorted row sums (f64)
__device__ __align__(16) float g_partial[2][2][NDET][NDET]; // [side][khalf] partials
__device__ __align__(16) unsigned int g_bits[2][NDET][16];  // packed mask rows
__device__ int           g_order[NDET];

// ---------------- 1. sigmoid-gather + inline rank + row sums (both sides) ---
// grid 512 x 256 thr: block n handles left AND right rows, float4 vectorized.
__global__ void prob_kernel(const float* __restrict__ left,
                            const float* __restrict__ right,
                            const float* __restrict__ scores,
                            const int*   __restrict__ labels,
                            float*       __restrict__ out) {
    int n = blockIdx.x;
    int tid = threadIdx.x;

    // rank of n under stable argsort(-scores)
    __shared__ int s_cnt;
    if (tid == 0) s_cnt = 0;
    __syncthreads();
    float sn = __ldg(&scores[n]);
    int c = 0;
    for (int j = tid; j < NDET; j += 256) {
        float sj = __ldg(&scores[j]);
        c += (sj > sn) || (sj == sn && j < n);
    }
    for (int o = 16; o; o >>= 1) c += __shfl_down_sync(0xffffffffu, c, o);
    if ((tid & 31) == 0) atomicAdd(&s_cnt, c);
    __syncthreads();
    int r = s_cnt;
    if (tid == 0) g_order[r] = n;

    int cls = labels[n];
    __shared__ double red[8];
#pragma unroll
    for (int side = 0; side < 2; ++side) {
        const float* base = side ? right : left;
        const float4* row = (const float4*)(base + ((size_t)n * NC + cls) * HW);
        float4* orow = (float4*)(out + ((size_t)side * NDET + n) * HW);
        float4* prow = (float4*)g_Pf[side][r];

        double s = 0.0;
        if (tid < HW4) {
            float4 x = row[tid];
            float4 p;
            p.x = 1.0f / (1.0f + expf(-x.x));
            p.y = 1.0f / (1.0f + expf(-x.y));
            p.z = 1.0f / (1.0f + expf(-x.z));
            p.w = 1.0f / (1.0f + expf(-x.w));
            orow[tid] = p;
            prow[tid] = p;
            s = ((double)p.x + (double)p.y) + ((double)p.z + (double)p.w);
        }
        for (int o = 16; o; o >>= 1) s += __shfl_down_sync(0xffffffffu, s, o);
        if ((tid & 31) == 0) red[tid >> 5] = s;
        __syncthreads();
        if (tid == 0) {
            double tt = 0.0;
#pragma unroll
            for (int w = 0; w < 8; ++w) tt += red[w];
            g_ud[side][r] = tt;
        }
        __syncthreads();
    }
}

// ---------------- 2. f32 Gram partials: compact tri grid + reg prefetch -----
// grid 144 linear: blockIdx.x = z*NTILE + t, z = side*2 + khalf. All blocks live.
__global__ void __launch_bounds__(256) gemm_partial_kernel() {
    int t = blockIdx.x % NTILE;
    int z = blockIdx.x / NTILE;
    int khalf = z & 1, side = z >> 1;
    int by = 0, rem = t;
    while (rem >= 8 - by) { rem -= 8 - by; ++by; }
    int bx = by + rem;                 // bx >= by (upper triangle)
    int arow0 = by * 64, brow0 = bx * 64;
    int kbeg = khalf ? 400 : 0;
    int kend = khalf ? HW : 400;

    __shared__ __align__(16) float As[16][68];
    __shared__ __align__(16) float Bs[16][68];
    int tid = threadIdx.x;
    int tx = tid & 15, ty = tid >> 4;
    const float* P = &g_Pf[side][0][0];

    float s[4][4];
#pragma unroll
    for (int m = 0; m < 4; ++m)
#pragma unroll
        for (int n = 0; n < 4; ++n) s[m][n] = 0.0f;

    int rr = tid >> 2, kq = (tid & 3) * 4;
    const float* aptr = &P[(size_t)(arow0 + rr) * HW + kq];
    const float* bptr = &P[(size_t)(brow0 + rr) * HW + kq];

    float4 av = *(const float4*)&aptr[kbeg];
    float4 bv = *(const float4*)&bptr[kbeg];
    for (int kt = kbeg; kt < kend; kt += 16) {
        As[kq + 0][rr] = av.x; As[kq + 1][rr] = av.y;
        As[kq + 2][rr] = av.z; As[kq + 3][rr] = av.w;
        Bs[kq + 0][rr] = bv.x; Bs[kq + 1][rr] = bv.y;
        Bs[kq + 2][rr] = bv.z; Bs[kq + 3][rr] = bv.w;
        __syncthreads();
        if (kt + 16 < kend) {           // prefetch next k-tile during compute
            av = *(const float4*)&aptr[kt + 16];
            bv = *(const float4*)&bptr[kt + 16];
        }
        float tacc[4][4];
#pragma unroll
        for (int m = 0; m < 4; ++m)
#pragma unroll
            for (int n = 0; n < 4; ++n) tacc[m][n] = 0.0f;
#pragma unroll
        for (int kk = 0; kk < 16; ++kk) {
            float4 a4 = *(const float4*)&As[kk][ty * 4];
            float4 b4 = *(const float4*)&Bs[kk][tx * 4];
            float a[4] = {a4.x, a4.y, a4.z, a4.w};
            float bb[4] = {b4.x, b4.y, b4.z, b4.w};
#pragma unroll
            for (int m = 0; m < 4; ++m)
#pragma unroll
                for (int n = 0; n < 4; ++n) tacc[m][n] = fmaf(a[m], bb[n], tacc[m][n]);
        }
#pragma unroll
        for (int m = 0; m < 4; ++m)
#pragma unroll
            for (int n = 0; n < 4; ++n) s[m][n] = __fadd_rn(s[m][n], tacc[m][n]);
        __syncthreads();
    }

    float* dst = &g_partial[side][khalf][0][0];
#pragma unroll
    for (int m = 0; m < 4; ++m) {
        int gi = arow0 + ty * 4 + m;
        float4 v = make_float4(s[m][0], s[m][1], s[m][2], s[m][3]);
        *(float4*)&dst[(size_t)gi * NDET + brow0 + tx * 4] = v;
    }
}

// ---------------- 3. epilogue: combine, threshold, INLINE f64 refine, pack --
// grid (256, 2), 256 threads: 2 rows/block; warps 0-3 row0, warps 4-7 row1.
__global__ void epilogue_kernel() {
    int side = blockIdx.y;
    int tid = threadIdx.x;
    int lane = tid & 31;
    int rloc = tid >> 7;                 // 0..1 (warp-uniform)
    int i = blockIdx.x * 2 + rloc;
    int tt = tid & 127;
    __shared__ unsigned int words[2][16];
    if (tid < 32) words[tid >> 4][tid & 15] = 0;
    __syncthreads();

    double den = g_ud[side][i] + EPSV;
    int j0 = tt * 4;
    float4 a = *(const float4*)&g_partial[side][0][i][j0];
    float4 b = *(const float4*)&g_partial[side][1][i][j0];
    float pa[4] = {a.x, a.y, a.z, a.w};
    float pb[4] = {b.x, b.y, b.z, b.w};
    unsigned int nib = 0, pend = 0;
#pragma unroll
    for (int n = 0; n < 4; ++n) {
        double inter = (double)pa[n] + (double)pb[n];
        double mg = inter - 0.5 * den;
        if (mg >= 0.0) nib |= (1u << n);
        if (j0 + n > i && fabs(mg) <= TAU * den) pend |= (1u << n);
    }

    // warp-cooperative exact refinement of flagged pairs (i is warp-uniform)
    const float4* Pi = (const float4*)g_Pf[side][i];
    while (true) {
        unsigned int bal = __ballot_sync(0xffffffffu, pend != 0u);
        if (!bal) break;
        int src = __ffs(bal) - 1;
        unsigned int pw = __shfl_sync(0xffffffffu, pend, src);
        int n = __ffs(pw) - 1;
        int gj = __shfl_sync(0xffffffffu, j0, src) + n;
        const float4* Pj = (const float4*)g_Pf[side][gj];
        double s0 = 0.0, s1 = 0.0, s2 = 0.0, s3 = 0.0;
#pragma unroll
        for (int q = 0; q < 7; ++q) {           // 196 float4 per row
            int k = lane + q * 32;
            float4 x = (k < HW4) ? Pi[k] : make_float4(0.f, 0.f, 0.f, 0.f);
            float4 y = (k < HW4) ? Pj[k] : make_float4(0.f, 0.f, 0.f, 0.f);
            s0 = fma((double)x.x, (double)y.x, s0);
            s1 = fma((double)x.y, (double)y.y, s1);
            s2 = fma((double)x.z, (double)y.z, s2);
            s3 = fma((double)x.w, (double)y.w, s3);
        }
        double sum = (s0 + s1) + (s2 + s3);
        for (int o = 16; o; o >>= 1) sum += __shfl_down_sync(0xffffffffu, sum, o);
        sum = __shfl_sync(0xffffffffu, sum, 0);
        if (lane == src) {
            if (sum / den >= NMS_THRESH) nib |= (1u << n);
            else                         nib &= ~(1u << n);
            pend &= ~(1u << n);
        }
    }

    atomicOr(&words[rloc][tt >> 3], nib << ((tt & 7) * 4));
    __syncthreads();
    if (tid < 32)
        g_bits[side][blockIdx.x * 2 + (tid >> 4)][tid & 15] = words[tid >> 4][tid & 15];
}

// ---------------- 4. skip-NMS with smem-staged bits + finalize, one block ---
__global__ void nmsfin_kernel(float* __restrict__ out, int out_size) {
    int tid = threadIdx.x;
    int lane = tid & 31;
    int warp = tid >> 5;
    __shared__ unsigned int rb[NDET * 16];      // 32 KB, reused per side
    __shared__ unsigned int s_sup[2][16];

#pragma unroll
    for (int side = 0; side < 2; ++side) {
        // parallel stage: 512 threads x 4 uint4 = 32 KB in one burst
        const uint4* src = (const uint4*)&g_bits[side][0][0];
        for (int q = tid; q < NDET * 4; q += NDET) ((uint4*)rb)[q] = src[q];
        __syncthreads();

        if (warp == 0) {
            unsigned int removed = 0;   // lane w<16 holds suppression word w
            int i = 0;                  // top-ranked row always kept
            while (true) {
                int rw = i >> 5, rbit = i & 31;
                unsigned int hi = (rbit == 31) ? 0u : (0xFFFFFFFFu << (rbit + 1));
                unsigned int m = (lane < 16) ? rb[i * 16 + lane] : 0u;
                if (lane < rw) m = 0u;
                else if (lane == rw) m &= hi;
                removed |= m;
                unsigned int cand = (lane < 16) ? ~removed : 0u;
                if (lane < rw) cand = 0u;
                else if (lane == rw) cand &= hi;
                unsigned int ball = __ballot_sync(0xffffffffu, cand != 0u);
                if (!ball) break;
                int w = __ffs(ball) - 1;
                unsigned int word = __shfl_sync(0xffffffffu, cand, w);
                i = w * 32 + __ffs(word) - 1;
            }
            if (lane < 16) s_sup[side][lane] = removed;
        }
        __syncthreads();
    }

    int r = tid;
    int n = g_order[r];
    bool valid = (g_ud[0][r] > 0.0) && (g_ud[1][r] > 0.0);
    bool supL = (s_sup[0][r >> 5] >> (r & 31)) & 1u;
    bool supR = (s_sup[1][r >> 5] >> (r & 31)) & 1u;
    float k = (valid && !supL && !supR) ? 1.0f : 0.0f;
    if (out_size >= 2 * NDET * HW + NDET)
        out[2 * NDET * HW + n] = k;
}

// ---------------- launch -----------------------------------------------------
extern "C" void kernel_launch(void* const* d_in, const int* in_sizes, int n_in,
                              void* d_out, int out_size) {
    const float* left   = (const float*)d_in[0];
    const float* right  = (const float*)d_in[1];
    const float* scores = (const float*)d_in[2];
    const int*   labels = (const int*)d_in[3];
    float* out = (float*)d_out;
    (void)in_sizes; (void)n_in;

    prob_kernel<<<NDET, 256>>>(left, right, scores, labels, out);
    gemm_partial_kernel<<<4 * NTILE, 256>>>();
    dim3 egrid(NDET / 2, 2);
    epilogue_kernel<<<egrid, 256>>>();
    nmsfin_kernel<<<1, NDET>>>(out, out_size);
}